// round 10
// baseline (speedup 1.0000x reference)
#include <cuda_runtime.h>
#include <cuda_bf16.h>
#include <cuda_fp16.h>

// Problem constants (fixed shapes for BevPoolV2_8478265442577)
#define B_     1
#define N_CAM  6
#define D_BINS 118
#define HF     32
#define WF     88
#define C_     80
#define DZ     1
#define DY     128
#define DX     128

#define N_DEPTH (B_ * N_CAM * D_BINS * HF * WF)   // 1,993,728
#define N_FEAT  (B_ * N_CAM * HF * WF * C_)       // 1,351,680
#define N_PTS   1000000
#define S_      (DZ * DY * DX)                    // 16,384
#define N_OUT4  (B_ * C_ * S_ / 4)                // 327,680 float4 in output
#define N_FEAT4 (N_FEAT / 4)                      // 337,920 float4 in feat

// fp16 mirror of feat: 80 halves per row = 160 B per row (20 x uint2)
__device__ __align__(16) static __half g_feat16[N_FEAT];
// per-point pre-gathered (depth scalar, feat row id)
__device__ __align__(8)  static uint2  g_pair[N_PTS];

// ---------------------------------------------------------------------------
// Fused preamble:
//   - zero the output
//   - build fp16 feat mirror
//   - pre-gather per-point (depth[rd[p]], rf[p]) pairs (random sector loads
//     live here, where MLP is unbounded and latency fully hidden)
// ---------------------------------------------------------------------------
__global__ void __launch_bounds__(256)
prep_kernel(float4* __restrict__ out, const float4* __restrict__ src,
            const float* __restrict__ depth,
            const int*   __restrict__ ranks_depth,
            const int*   __restrict__ ranks_feat) {
    const int tid    = blockIdx.x * blockDim.x + threadIdx.x;
    const int stride = gridDim.x * blockDim.x;
    uint2* __restrict__ dst = (uint2*)g_feat16;

    for (int i = tid; i < N_OUT4; i += stride)
        out[i] = make_float4(0.f, 0.f, 0.f, 0.f);

    for (int i = tid; i < N_FEAT4; i += stride) {
        float4 v = src[i];
        __half2 h0 = __floats2half2_rn(v.x, v.y);
        __half2 h1 = __floats2half2_rn(v.z, v.w);
        uint2 u;
        u.x = *reinterpret_cast<unsigned int*>(&h0);
        u.y = *reinterpret_cast<unsigned int*>(&h1);
        dst[i] = u;
    }

    for (int p = tid; p < N_PTS; p += stride) {
        int rd = __ldg(&ranks_depth[p]);
        int rf = __ldg(&ranks_feat[p]);
        float d = __ldg(&depth[rd]);
        g_pair[p] = make_uint2(__float_as_uint(d), (unsigned int)rf);
    }
}

// ---------------------------------------------------------------------------
// One warp per interval. Lane l (0..19) owns channels [4l, 4l+4).
// Per 32-point chunk:
//   - 1 coalesced LDG.64: all 32 lanes read the (d, rf) pair for one point
//     (out-of-range lanes padded with d=0, rf=0 -> multiply-by-zero)
//   - inner loop 4 points per group -> 4 independent LDG.64 (fp16 feat)
// Intervals are disjoint BEV bins -> plain stores, no atomics.
// ---------------------------------------------------------------------------
__global__ void __launch_bounds__(256)
bev_pool_kernel(const int* __restrict__ ranks_bev,
                const int* __restrict__ istart,
                const int* __restrict__ ilen,
                int n_intervals,
                float* __restrict__ out) {
    int gwarp = (blockIdx.x * blockDim.x + threadIdx.x) >> 5;
    int lane  = threadIdx.x & 31;
    if (gwarp >= n_intervals) return;

    const int start = istart[gwarp];
    const int len   = ilen[gwarp];

    const bool fa = (lane < 20);                 // feat-active lanes (20*4 = 80 ch)
    const uint2* __restrict__ fbase = (const uint2*)g_feat16;  // row stride 20
    const uint2* __restrict__ pbase = g_pair + start;

    float4 acc = make_float4(0.f, 0.f, 0.f, 0.f);

    for (int base = 0; base < len; base += 32) {
        const int off = base + lane;
        uint2 pr = make_uint2(0u, 0u);
        if (off < len) pr = __ldg(pbase + off);
        const float dv  = __uint_as_float(pr.x);
        const int   rfv = (int)pr.y;

        #pragma unroll
        for (int j = 0; j < 32; j += 4) {
            float d0 = __shfl_sync(0xffffffffu, dv, j + 0);
            float d1 = __shfl_sync(0xffffffffu, dv, j + 1);
            float d2 = __shfl_sync(0xffffffffu, dv, j + 2);
            float d3 = __shfl_sync(0xffffffffu, dv, j + 3);
            int rf0 = __shfl_sync(0xffffffffu, rfv, j + 0);
            int rf1 = __shfl_sync(0xffffffffu, rfv, j + 1);
            int rf2 = __shfl_sync(0xffffffffu, rfv, j + 2);
            int rf3 = __shfl_sync(0xffffffffu, rfv, j + 3);
            if (fa) {
                // 4 independent 64-bit fp16 gathers in flight
                uint2 u0 = __ldg(fbase + (size_t)rf0 * 20 + lane);
                uint2 u1 = __ldg(fbase + (size_t)rf1 * 20 + lane);
                uint2 u2 = __ldg(fbase + (size_t)rf2 * 20 + lane);
                uint2 u3 = __ldg(fbase + (size_t)rf3 * 20 + lane);

                float2 a0 = __half22float2(*reinterpret_cast<__half2*>(&u0.x));
                float2 b0 = __half22float2(*reinterpret_cast<__half2*>(&u0.y));
                float2 a1 = __half22float2(*reinterpret_cast<__half2*>(&u1.x));
                float2 b1 = __half22float2(*reinterpret_cast<__half2*>(&u1.y));
                float2 a2 = __half22float2(*reinterpret_cast<__half2*>(&u2.x));
                float2 b2 = __half22float2(*reinterpret_cast<__half2*>(&u2.y));
                float2 a3 = __half22float2(*reinterpret_cast<__half2*>(&u3.x));
                float2 b3 = __half22float2(*reinterpret_cast<__half2*>(&u3.y));

                acc.x = fmaf(d0, a0.x, acc.x);
                acc.y = fmaf(d0, a0.y, acc.y);
                acc.z = fmaf(d0, b0.x, acc.z);
                acc.w = fmaf(d0, b0.y, acc.w);
                acc.x = fmaf(d1, a1.x, acc.x);
                acc.y = fmaf(d1, a1.y, acc.y);
                acc.z = fmaf(d1, b1.x, acc.z);
                acc.w = fmaf(d1, b1.y, acc.w);
                acc.x = fmaf(d2, a2.x, acc.x);
                acc.y = fmaf(d2, a2.y, acc.y);
                acc.z = fmaf(d2, b2.x, acc.z);
                acc.w = fmaf(d2, b2.y, acc.w);
                acc.x = fmaf(d3, a3.x, acc.x);
                acc.y = fmaf(d3, a3.y, acc.y);
                acc.z = fmaf(d3, b3.x, acc.z);
                acc.w = fmaf(d3, b3.y, acc.w);
            }
        }
    }

    // ---- store: output layout (B, C, Dz, Dy, Dx); bev = b*S + s ----
    if (fa) {
        int bev = __ldg(&ranks_bev[start]);
        int b   = bev / S_;
        int s   = bev - b * S_;
        float* o = out + (size_t)b * C_ * S_ + s;
        int c = lane * 4;
        o[(size_t)(c + 0) * S_] = acc.x;
        o[(size_t)(c + 1) * S_] = acc.y;
        o[(size_t)(c + 2) * S_] = acc.z;
        o[(size_t)(c + 3) * S_] = acc.w;
    }
}

// ---------------------------------------------------------------------------
extern "C" void kernel_launch(void* const* d_in, const int* in_sizes, int n_in,
                              void* d_out, int out_size) {
    const float* depth = nullptr;
    const float* feat  = nullptr;
    const int*   ranks[3] = {nullptr, nullptr, nullptr};
    int nrk = 0;
    const int* small_arr[2] = {nullptr, nullptr};
    int small_sz[2] = {0, 0};
    int nsmall = 0;

    for (int i = 0; i < n_in; i++) {
        int sz = in_sizes[i];
        if (sz == N_DEPTH && !depth) {
            depth = (const float*)d_in[i];
        } else if (sz == N_FEAT && !feat) {
            feat = (const float*)d_in[i];
        } else if (sz == N_PTS && nrk < 3) {
            ranks[nrk++] = (const int*)d_in[i];   // order: depths, feats, bevs
        } else if (sz == 5) {
            // bev_feat_shape metadata — compile-time constants here
        } else if (nsmall < 2) {
            small_arr[nsmall] = (const int*)d_in[i];  // order: starts, lengths
            small_sz[nsmall] = sz;
            nsmall++;
        }
    }

    const int* istart = small_arr[0];
    const int* ilen   = small_arr[1];
    int n_intervals   = small_sz[0];

    float* out = (float*)d_out;

    // 1) fused preamble: zero output + fp16 feat mirror + (d, rf) pre-gather
    prep_kernel<<<2048, 256>>>((float4*)out, (const float4*)feat,
                               depth, ranks[0], ranks[1]);

    // 2) pooled gather-multiply-store, one warp per interval
    const int threads = 256;                    // 8 warps per block
    int blocks = (n_intervals + 7) / 8;
    if (blocks < 1) blocks = 1;
    bev_pool_kernel<<<blocks, threads>>>(ranks[2],
                                         istart, ilen, n_intervals, out);
}

// round 11
// speedup vs baseline: 1.3282x; 1.3282x over previous
#include <cuda_runtime.h>
#include <cuda_bf16.h>
#include <cuda_fp16.h>

// Problem constants (fixed shapes for BevPoolV2_8478265442577)
#define B_     1
#define N_CAM  6
#define D_BINS 118
#define HF     32
#define WF     88
#define C_     80
#define DZ     1
#define DY     128
#define DX     128

#define N_DEPTH (B_ * N_CAM * D_BINS * HF * WF)   // 1,993,728
#define N_FEAT  (B_ * N_CAM * HF * WF * C_)       // 1,351,680
#define N_PTS   1000000
#define S_      (DZ * DY * DX)                    // 16,384
#define N_OUT4  (B_ * C_ * S_ / 4)                // 327,680 float4 in output
#define N_FEAT4 (N_FEAT / 4)                      // 337,920 float4 in feat

// fp16 mirror of feat: 80 halves per row = 160 B per row (10 x uint4)
__device__ __align__(16) static __half g_feat16[N_FEAT];

// ---------------------------------------------------------------------------
// Fused preamble: zero the output AND build the fp16 feat mirror.
// ---------------------------------------------------------------------------
__global__ void __launch_bounds__(256)
prep_kernel(float4* __restrict__ out, const float4* __restrict__ src) {
    const int tid    = blockIdx.x * blockDim.x + threadIdx.x;
    const int stride = gridDim.x * blockDim.x;
    uint2* __restrict__ dst = (uint2*)g_feat16;

    for (int i = tid; i < N_OUT4; i += stride)
        out[i] = make_float4(0.f, 0.f, 0.f, 0.f);

    for (int i = tid; i < N_FEAT4; i += stride) {
        float4 v = src[i];
        __half2 h0 = __floats2half2_rn(v.x, v.y);
        __half2 h1 = __floats2half2_rn(v.z, v.w);
        uint2 u;
        u.x = *reinterpret_cast<unsigned int*>(&h0);
        u.y = *reinterpret_cast<unsigned int*>(&h1);
        dst[i] = u;
    }
}

// half2 (as uint) -> float2
__device__ __forceinline__ float2 h2f(unsigned int h) {
    return __half22float2(*reinterpret_cast<const __half2*>(&h));
}

// ---------------------------------------------------------------------------
// One warp per interval, THREE points per inner iteration.
// Lane groups: {0-9}, {10-19}, {20-29} each own a full 80-ch feat row as
// 10 x uint4 (8 fp16 channels per lane). Lanes 30-31 shadow group 2.
// Per 30-point chunk: 3 scalar LDGs (rd, rf, depth gather) by lanes 0-29.
// Per inner iter (3 points): 2 SHFL (per-lane src) + 1 LDG.128 + 8 F2F + 8 FMA.
// Cross-group shuffle reduction per interval merges the 3 partial sums.
// Intervals are disjoint BEV bins -> plain stores, no atomics.
// ---------------------------------------------------------------------------
__global__ void __launch_bounds__(256)
bev_pool_kernel(const float* __restrict__ depth,
                const int*   __restrict__ ranks_depth,
                const int*   __restrict__ ranks_feat,
                const int*   __restrict__ ranks_bev,
                const int*   __restrict__ istart,
                const int*   __restrict__ ilen,
                int n_intervals,
                float* __restrict__ out) {
    const int gwarp = (blockIdx.x * blockDim.x + threadIdx.x) >> 5;
    const int lane  = threadIdx.x & 31;
    if (gwarp >= n_intervals) return;

    const int start = istart[gwarp];
    const int len   = ilen[gwarp];

    // group id (0,1,2) and lane-within-group (0..9); lanes 30,31 shadow grp 2
    const int grp = (lane >= 30) ? 2 : (lane / 10);
    const int fl  = (lane >= 30) ? (lane - 30) : (lane - grp * 10);

    const uint4* __restrict__ fbase = (const uint4*)g_feat16;  // row = 10 uint4

    // 8 channel accumulators (channels fl*8 .. fl*8+7)
    float2 a0 = make_float2(0.f, 0.f);
    float2 a1 = make_float2(0.f, 0.f);
    float2 a2 = make_float2(0.f, 0.f);
    float2 a3 = make_float2(0.f, 0.f);

    for (int base = 0; base < len; base += 30) {
        // ---- chunk scalars: lanes 0-29 load (rd, rf) and gather depth ----
        const int off = base + lane;
        float dv  = 0.f;
        int   rfv = 0;
        if (lane < 30 && off < len) {
            const int p = start + off;
            int rd = __ldg(&ranks_depth[p]);
            rfv    = __ldg(&ranks_feat[p]);
            dv     = __ldg(&depth[rd]);
        }

        #pragma unroll
        for (int j = 0; j < 30; j += 3) {
            const int src = j + grp;                       // per-lane source
            const float d  = __shfl_sync(0xffffffffu, dv,  src);
            const int   rf = __shfl_sync(0xffffffffu, rfv, src);
            const uint4 u = __ldg(fbase + (size_t)rf * 10 + fl);
            const float2 f0 = h2f(u.x);
            const float2 f1 = h2f(u.y);
            const float2 f2 = h2f(u.z);
            const float2 f3 = h2f(u.w);
            a0.x = fmaf(d, f0.x, a0.x);
            a0.y = fmaf(d, f0.y, a0.y);
            a1.x = fmaf(d, f1.x, a1.x);
            a1.y = fmaf(d, f1.y, a1.y);
            a2.x = fmaf(d, f2.x, a2.x);
            a2.y = fmaf(d, f2.y, a2.y);
            a3.x = fmaf(d, f3.x, a3.x);
            a3.y = fmaf(d, f3.y, a3.y);
        }
    }

    // ---- merge the 3 group partials into lanes 0-9 ----
    float v[8] = {a0.x, a0.y, a1.x, a1.y, a2.x, a2.y, a3.x, a3.y};
    #pragma unroll
    for (int k = 0; k < 8; k++) {
        float t1 = __shfl_sync(0xffffffffu, v[k], lane + 10);
        float t2 = __shfl_sync(0xffffffffu, v[k], lane + 20);
        v[k] += t1 + t2;      // valid for lanes 0-9
    }

    // ---- store: output layout (B, C, Dz, Dy, Dx); bev = b*S + s ----
    if (lane < 10) {
        int bev = __ldg(&ranks_bev[start]);
        int b   = bev / S_;
        int s   = bev - b * S_;
        float* o = out + (size_t)b * C_ * S_ + s;
        const int c = lane * 8;
        #pragma unroll
        for (int k = 0; k < 8; k++)
            o[(size_t)(c + k) * S_] = v[k];
    }
}

// ---------------------------------------------------------------------------
extern "C" void kernel_launch(void* const* d_in, const int* in_sizes, int n_in,
                              void* d_out, int out_size) {
    const float* depth = nullptr;
    const float* feat  = nullptr;
    const int*   ranks[3] = {nullptr, nullptr, nullptr};
    int nrk = 0;
    const int* small_arr[2] = {nullptr, nullptr};
    int small_sz[2] = {0, 0};
    int nsmall = 0;

    for (int i = 0; i < n_in; i++) {
        int sz = in_sizes[i];
        if (sz == N_DEPTH && !depth) {
            depth = (const float*)d_in[i];
        } else if (sz == N_FEAT && !feat) {
            feat = (const float*)d_in[i];
        } else if (sz == N_PTS && nrk < 3) {
            ranks[nrk++] = (const int*)d_in[i];   // order: depths, feats, bevs
        } else if (sz == 5) {
            // bev_feat_shape metadata — compile-time constants here
        } else if (nsmall < 2) {
            small_arr[nsmall] = (const int*)d_in[i];  // order: starts, lengths
            small_sz[nsmall] = sz;
            nsmall++;
        }
    }

    const int* istart = small_arr[0];
    const int* ilen   = small_arr[1];
    int n_intervals   = small_sz[0];

    float* out = (float*)d_out;

    // 1) fused preamble: zero output + build fp16 feat mirror (full-chip wave)
    prep_kernel<<<2048, 256>>>((float4*)out, (const float4*)feat);

    // 2) pooled gather-multiply-store, one warp per interval, 3 pts/iter
    const int threads = 256;                    // 8 warps per block
    int blocks = (n_intervals + 7) / 8;
    if (blocks < 1) blocks = 1;
    bev_pool_kernel<<<blocks, threads>>>(depth,
                                         ranks[0], ranks[1], ranks[2],
                                         istart, ilen, n_intervals, out);
}